// round 8
// baseline (speedup 1.0000x reference)
#include <cuda_runtime.h>
#include <math.h>

// Cox partial likelihood (Breslow ties, mean reduction) via time-bucket histogram.
// time ∈ [0, 65536):
//   S[t] = sum_{time_i==t} exp(x_i),  m[t] = #events at t
//   D[t] = suffix sum of S,  loss = (sum_t m[t]*log(D[t]+eps) - sum_ev x)/(n_ev+eps)
//
// Round 7: SINGLE PASS, no smem histogram. Each element issues ONE u64
// global RED (no return) into a 64K-entry packed table:
//   bits [0,40)  = round(exp(x)*2048)   (fixed point, exact integer sum)
//   bits [40,64) = event count
// Global REDG lanes (~1.3 cyc/lane/SM, 184 LTS slices chip-wide) replace smem
// ATOMS lanes (~2 cyc/lane/SM) AND halve loads/visits (one pass, 96MB once).
// All sums integer/fixed-order -> bitwise deterministic, graph-replay safe.

#define NB      65536
#define G       148
#define TPB     1024
#define NCHUNK  256
#define INVSCALE (1.0 / 2048.0)

__device__ unsigned long long g_tab[NB];      // packed table (512KB, L2-resident)
__device__ double   g_chunkS[NCHUNK];         // per-chunk exp-sum
__device__ double   g_chunkNll[NCHUNK];
__device__ unsigned g_chunkM[NCHUNK];
__device__ float    g_evx[G];                 // per-CTA sum of event logits
__device__ unsigned g_barCnt[4];              // monotone barrier counters (replay-safe)

// ---------------------------------------------------------------------------
__device__ __forceinline__ void grid_barrier(int b) {
    __syncthreads();
    if (threadIdx.x == 0) {
        __threadfence();
        unsigned ticket = atomicAdd(&g_barCnt[b], 1u);
        unsigned target = (ticket / G + 1u) * G;
        while (atomicAdd(&g_barCnt[b], 0u) < target) __nanosleep(64);
    }
    __syncthreads();
}

__device__ __forceinline__ double blockReduceD(double v, double* scr) {
    int lane = threadIdx.x & 31, wid = threadIdx.x >> 5;
    #pragma unroll
    for (int o = 16; o > 0; o >>= 1) v += __shfl_down_sync(0xffffffffu, v, o);
    if (lane == 0) scr[wid] = v;
    __syncthreads();
    v = (wid == 0 && lane < TPB / 32) ? scr[lane] : 0.0;
    if (wid == 0) {
        #pragma unroll
        for (int o = 16; o > 0; o >>= 1) v += __shfl_down_sync(0xffffffffu, v, o);
    }
    return v;   // valid in thread 0
}

// ---------------------------------------------------------------------------
__device__ __forceinline__ void elem(int t, float xv, int sv, float& ev_x) {
    // round(exp(x)*2048) = round(2^(x*log2e + 11))
    unsigned fix = __float2uint_rn(exp2f(fmaf(xv, 1.44269504f, 11.0f)));
    unsigned long long payload =
        (unsigned long long)fix | ((unsigned long long)(unsigned)sv << 40);
    atomicAdd(&g_tab[t], payload);          // no return -> REDG.ADD.64
    if (sv) ev_x += xv;
}

// ---------------------------------------------------------------------------
__global__ void __launch_bounds__(TPB, 1)
mega_kernel(const float* __restrict__ x,
            const int*   __restrict__ st,
            const int*   __restrict__ tm,
            float* __restrict__ out,
            int n, int lenPer) {
    __shared__ double sm_buf[TPB];      // phase-3 suffix buffer
    __shared__ double sm_scr[32];
    __shared__ double sm_off;

    int tid = threadIdx.x;
    int c   = blockIdx.x;

    // ---------------- Phase 0: zero the packed table ----------------
    {
        int idx = c * TPB + tid;        // grid covers 151552 >= 65536
        if (idx < NB) g_tab[idx] = 0ull;
    }
    grid_barrier(0);

    // ---------------- Phase 1: single-pass packed global-RED histogram ----
    float ev_x = 0.0f;
    {
        int s0 = min(c * lenPer, n);    // lenPer multiple of 4
        int s1 = min(s0 + lenPer, n);
        int nfull4 = (s1 - s0) >> 2;

        int g = tid;
        for (; g + TPB < nfull4; g += 2 * TPB) {
            int idx0 = s0 + g * 4;
            int idx1 = s0 + (g + TPB) * 4;
            // front-batched streaming loads (no reuse)
            float4 xa = __ldcs((const float4*)(x  + idx0));
            float4 xb = __ldcs((const float4*)(x  + idx1));
            int4   ta = __ldcs((const int4*)  (tm + idx0));
            int4   tb = __ldcs((const int4*)  (tm + idx1));
            int4   sa = __ldcs((const int4*)  (st + idx0));
            int4   sb = __ldcs((const int4*)  (st + idx1));
            elem(ta.x, xa.x, sa.x, ev_x);
            elem(ta.y, xa.y, sa.y, ev_x);
            elem(ta.z, xa.z, sa.z, ev_x);
            elem(ta.w, xa.w, sa.w, ev_x);
            elem(tb.x, xb.x, sb.x, ev_x);
            elem(tb.y, xb.y, sb.y, ev_x);
            elem(tb.z, xb.z, sb.z, ev_x);
            elem(tb.w, xb.w, sb.w, ev_x);
        }
        for (; g < nfull4; g += TPB) {
            int idx = s0 + g * 4;
            float4 xv = __ldcs((const float4*)(x  + idx));
            int4   tv = __ldcs((const int4*)  (tm + idx));
            int4   sv = __ldcs((const int4*)  (st + idx));
            elem(tv.x, xv.x, sv.x, ev_x);
            elem(tv.y, xv.y, sv.y, ev_x);
            elem(tv.z, xv.z, sv.z, ev_x);
            elem(tv.w, xv.w, sv.w, ev_x);
        }
        int tail0 = s0 + nfull4 * 4;
        if (tid < s1 - tail0) {
            int idx = tail0 + tid;
            elem(tm[idx], x[idx], st[idx], ev_x);
        }
    }
    {
        double evd = blockReduceD((double)ev_x, sm_scr);
        if (tid == 0) g_evx[c] = (float)evd;
    }
    grid_barrier(1);

    // ---------------- Phase 2: per-chunk sums (256 chunks of 256 buckets) ---
    for (int ch = c; ch < NCHUNK; ch += G) {
        unsigned long long p = 0ull;
        if (tid < 256) p = __ldcg(&g_tab[ch * 256 + tid]);
        double s = (double)(p & 0xFFFFFFFFFFull);
        double m = (double)(p >> 40);
        __syncthreads();
        double ds = blockReduceD(s, sm_scr);
        __syncthreads();
        double dm = blockReduceD(m, sm_scr);
        if (tid == 0) {
            g_chunkS[ch] = ds * INVSCALE;
            g_chunkM[ch] = (unsigned)(dm + 0.5);
        }
        __syncthreads();
    }
    grid_barrier(2);

    // ---------------- Phase 3: per-chunk suffix scan + nll ----------------
    for (int ch = c; ch < NCHUNK; ch += G) {
        // exclusive suffix offset over later chunks
        double cv = (tid < NCHUNK && tid > ch) ? __ldcg(&g_chunkS[tid]) : 0.0;
        double off = blockReduceD(cv, sm_scr);
        if (tid == 0) sm_off = off;
        __syncthreads();

        double sv = 0.0; unsigned m = 0;
        if (tid < 256) {
            unsigned long long p = __ldcg(&g_tab[ch * 256 + tid]);
            sv = (double)(p & 0xFFFFFFFFFFull) * INVSCALE;
            m  = (unsigned)(p >> 40);
        }
        sm_buf[tid] = sv;
        __syncthreads();
        for (int o = 1; o < TPB; o <<= 1) {
            double v = (tid + o < TPB) ? sm_buf[tid + o] : 0.0;
            __syncthreads();
            sm_buf[tid] += v;
            __syncthreads();
        }
        double nll = 0.0;
        if (tid < 256 && m) {
            double D = sm_buf[tid] + sm_off;
            nll = (double)m * log(D + 1e-12);
        }
        __syncthreads();
        double tot = blockReduceD(nll, sm_scr);
        if (tid == 0) g_chunkNll[ch] = tot;
        __syncthreads();
    }
    grid_barrier(3);

    // ---------------- Phase 4: CTA 0 combines ----------------
    if (c == 0) {
        double a = (tid < NCHUNK) ? __ldcg(&g_chunkNll[tid]) : 0.0;
        double b = (tid < NCHUNK) ? (double)__ldcg(&g_chunkM[tid]) : 0.0;
        double e = (tid < G) ? (double)__ldcg(&g_evx[tid]) : 0.0;
        double nll = blockReduceD(a, sm_scr); __syncthreads();
        double nev = blockReduceD(b, sm_scr); __syncthreads();
        double evx = blockReduceD(e, sm_scr);
        if (tid == 0)
            out[0] = (float)((nll - evx) / (nev + 1e-12));
    }
}

// ---------------------------------------------------------------------------
extern "C" void kernel_launch(void* const* d_in, const int* in_sizes, int n_in,
                              void* d_out, int out_size) {
    const float* logits = (const float*)d_in[0];
    const int*   status = (const int*)d_in[1];
    const int*   timev  = (const int*)d_in[2];
    float*       out    = (float*)d_out;
    int n = in_sizes[0];

    int lenPer = ((n + G - 1) / G + 3) & ~3;   // per-CTA slice, multiple of 4

    mega_kernel<<<G, TPB>>>(logits, status, timev, out, n, lenPer);
}

// round 10
// speedup vs baseline: 1.1386x; 1.1386x over previous
#include <cuda_runtime.h>
#include <math.h>

// Cox partial likelihood (Breslow ties, mean reduction) via time-bucket histogram.
// time ∈ [0, 65536):
//   S[t] = sum_{time_i==t} exp(x_i),  m[t] = #events at t
//   D[t] = suffix sum of S,  loss = (sum_t m[t]*log(D[t]+eps) - sum_ev x)/(n_ev+eps)
//
// Round 9 (= round 8 re-run after infra failure): single pass, ONE u64 global
// RED per element into a 16-WAY BANKED packed table (16 x 512KB = 8MB,
// L2-resident). Banking cuts same-address collisions from 128/addr (round 7's
// failure: LTS per-address serialization) to ~8 per (bucket,bank), arriving
// microseconds apart -> uncontended.
//   payload bits [0,40)  = round(exp(x)*2048)  (exact integer sum)
//   payload bits [40,64) = event count
// All sums integer/fixed-order -> bitwise deterministic, graph-replay safe.

#define NB      65536
#define NBANK   16
#define G       148
#define TPB     1024
#define NCHUNK  256
#define INVSCALE (1.0 / 2048.0)

__device__ unsigned long long g_tab[(size_t)NBANK * NB]; // banked packed tables (8MB)
__device__ unsigned long long g_mrg[NB];                 // merged table (512KB)
__device__ double   g_chunkS[NCHUNK];
__device__ double   g_chunkNll[NCHUNK];
__device__ unsigned g_chunkM[NCHUNK];
__device__ float    g_evx[G];                // per-CTA sum of event logits
__device__ unsigned g_barCnt[4];             // monotone barrier counters (replay-safe)

// ---------------------------------------------------------------------------
__device__ __forceinline__ void grid_barrier(int b) {
    __syncthreads();
    if (threadIdx.x == 0) {
        __threadfence();
        unsigned ticket = atomicAdd(&g_barCnt[b], 1u);
        unsigned target = (ticket / G + 1u) * G;
        while (atomicAdd(&g_barCnt[b], 0u) < target) __nanosleep(64);
    }
    __syncthreads();
}

__device__ __forceinline__ double blockReduceD(double v, double* scr) {
    int lane = threadIdx.x & 31, wid = threadIdx.x >> 5;
    #pragma unroll
    for (int o = 16; o > 0; o >>= 1) v += __shfl_down_sync(0xffffffffu, v, o);
    if (lane == 0) scr[wid] = v;
    __syncthreads();
    v = (wid == 0 && lane < TPB / 32) ? scr[lane] : 0.0;
    if (wid == 0) {
        #pragma unroll
        for (int o = 16; o > 0; o >>= 1) v += __shfl_down_sync(0xffffffffu, v, o);
    }
    return v;   // valid in thread 0
}

// ---------------------------------------------------------------------------
__device__ __forceinline__ void elem(int t, float xv, int sv,
                                     unsigned long long* bank, float& ev_x) {
    // round(exp(x)*2048) = round(2^(x*log2e + 11))
    unsigned fix = __float2uint_rn(exp2f(fmaf(xv, 1.44269504f, 11.0f)));
    unsigned long long payload =
        (unsigned long long)fix | ((unsigned long long)(unsigned)sv << 40);
    atomicAdd(bank + t, payload);           // no return -> REDG.ADD.64
    if (sv) ev_x += xv;
}

// ---------------------------------------------------------------------------
__global__ void __launch_bounds__(TPB, 1)
mega_kernel(const float* __restrict__ x,
            const int*   __restrict__ st,
            const int*   __restrict__ tm,
            float* __restrict__ out,
            int n, int lenPer) {
    __shared__ double             sm_buf[TPB];   // phase-3 suffix buffer
    __shared__ unsigned long long sm_u64[TPB];   // phase-2 merge buffer
    __shared__ double             sm_scr[32];
    __shared__ double             sm_off;

    int tid = threadIdx.x;
    int c   = blockIdx.x;

    // ---------------- Phase 0: zero the banked tables ----------------
    {
        size_t total = (size_t)NBANK * NB;
        for (size_t idx = (size_t)c * TPB + tid; idx < total; idx += (size_t)G * TPB)
            g_tab[idx] = 0ull;
    }
    grid_barrier(0);

    // ---------------- Phase 1: single-pass banked global-RED histogram ----
    float ev_x = 0.0f;
    {
        // per-warp bank: spreads same-bucket traffic over 16 copies
        unsigned long long* bank =
            g_tab + (size_t)((((unsigned)c << 5) + (tid >> 5)) & (NBANK - 1)) * NB;

        int s0 = min(c * lenPer, n);    // lenPer multiple of 4
        int s1 = min(s0 + lenPer, n);
        int nfull4 = (s1 - s0) >> 2;

        int g = tid;
        for (; g + TPB < nfull4; g += 2 * TPB) {
            int idx0 = s0 + g * 4;
            int idx1 = s0 + (g + TPB) * 4;
            float4 xa = __ldcs((const float4*)(x  + idx0));
            float4 xb = __ldcs((const float4*)(x  + idx1));
            int4   ta = __ldcs((const int4*)  (tm + idx0));
            int4   tb = __ldcs((const int4*)  (tm + idx1));
            int4   sa = __ldcs((const int4*)  (st + idx0));
            int4   sb = __ldcs((const int4*)  (st + idx1));
            elem(ta.x, xa.x, sa.x, bank, ev_x);
            elem(ta.y, xa.y, sa.y, bank, ev_x);
            elem(ta.z, xa.z, sa.z, bank, ev_x);
            elem(ta.w, xa.w, sa.w, bank, ev_x);
            elem(tb.x, xb.x, sb.x, bank, ev_x);
            elem(tb.y, xb.y, sb.y, bank, ev_x);
            elem(tb.z, xb.z, sb.z, bank, ev_x);
            elem(tb.w, xb.w, sb.w, bank, ev_x);
        }
        for (; g < nfull4; g += TPB) {
            int idx = s0 + g * 4;
            float4 xv = __ldcs((const float4*)(x  + idx));
            int4   tv = __ldcs((const int4*)  (tm + idx));
            int4   sv = __ldcs((const int4*)  (st + idx));
            elem(tv.x, xv.x, sv.x, bank, ev_x);
            elem(tv.y, xv.y, sv.y, bank, ev_x);
            elem(tv.z, xv.z, sv.z, bank, ev_x);
            elem(tv.w, xv.w, sv.w, bank, ev_x);
        }
        // uniform tail (robust for any n)
        int tail0 = s0 + nfull4 * 4;
        for (int idx = tail0 + tid; idx < s1; idx += TPB)
            elem(tm[idx], x[idx], st[idx], bank, ev_x);
    }
    {
        double evd = blockReduceD((double)ev_x, sm_scr);
        if (tid == 0) g_evx[c] = (float)evd;
    }
    grid_barrier(1);

    // ---------------- Phase 2: merge 16 banks + per-chunk sums ------------
    for (int ch = c; ch < NCHUNK; ch += G) {
        int i    = tid & 255;
        int part = tid >> 8;                  // 0..3, each sums 4 banks
        int t    = ch * 256 + i;
        unsigned long long acc = 0ull;
        #pragma unroll
        for (int b = 0; b < NBANK / 4; b++)
            acc += __ldcg(&g_tab[(size_t)(part + 4 * b) * NB + t]);
        sm_u64[tid] = acc;
        __syncthreads();
        unsigned long long tot = 0ull;
        if (part == 0) {
            tot = sm_u64[i] + sm_u64[i + 256] + sm_u64[i + 512] + sm_u64[i + 768];
            g_mrg[t] = tot;
        }
        __syncthreads();
        double s = (part == 0) ? (double)(tot & 0xFFFFFFFFFFull) : 0.0;
        double m = (part == 0) ? (double)(tot >> 40) : 0.0;
        double ds = blockReduceD(s, sm_scr);
        __syncthreads();
        double dm = blockReduceD(m, sm_scr);
        if (tid == 0) {
            g_chunkS[ch] = ds * INVSCALE;
            g_chunkM[ch] = (unsigned)(dm + 0.5);
        }
        __syncthreads();
    }
    grid_barrier(2);

    // ---------------- Phase 3: per-chunk suffix scan + nll ----------------
    for (int ch = c; ch < NCHUNK; ch += G) {
        // exclusive suffix offset over later chunks
        double cv = (tid < NCHUNK && tid > ch) ? __ldcg(&g_chunkS[tid]) : 0.0;
        double off = blockReduceD(cv, sm_scr);
        if (tid == 0) sm_off = off;
        __syncthreads();

        double sv = 0.0; unsigned m = 0;
        if (tid < 256) {
            unsigned long long p = __ldcg(&g_mrg[ch * 256 + tid]);
            sv = (double)(p & 0xFFFFFFFFFFull) * INVSCALE;
            m  = (unsigned)(p >> 40);
        }
        sm_buf[tid] = sv;
        __syncthreads();
        for (int o = 1; o < TPB; o <<= 1) {
            double v = (tid + o < TPB) ? sm_buf[tid + o] : 0.0;
            __syncthreads();
            sm_buf[tid] += v;
            __syncthreads();
        }
        double nll = 0.0;
        if (tid < 256 && m) {
            double D = sm_buf[tid] + sm_off;
            nll = (double)m * log(D + 1e-12);
        }
        __syncthreads();
        double tot = blockReduceD(nll, sm_scr);
        if (tid == 0) g_chunkNll[ch] = tot;
        __syncthreads();
    }
    grid_barrier(3);

    // ---------------- Phase 4: CTA 0 combines ----------------
    if (c == 0) {
        double a = (tid < NCHUNK) ? __ldcg(&g_chunkNll[tid]) : 0.0;
        double b = (tid < NCHUNK) ? (double)__ldcg(&g_chunkM[tid]) : 0.0;
        double e = (tid < G) ? (double)__ldcg(&g_evx[tid]) : 0.0;
        double nll = blockReduceD(a, sm_scr); __syncthreads();
        double nev = blockReduceD(b, sm_scr); __syncthreads();
        double evx = blockReduceD(e, sm_scr);
        if (tid == 0)
            out[0] = (float)((nll - evx) / (nev + 1e-12));
    }
}

// ---------------------------------------------------------------------------
extern "C" void kernel_launch(void* const* d_in, const int* in_sizes, int n_in,
                              void* d_out, int out_size) {
    const float* logits = (const float*)d_in[0];
    const int*   status = (const int*)d_in[1];
    const int*   timev  = (const int*)d_in[2];
    float*       out    = (float*)d_out;
    int n = in_sizes[0];

    int lenPer = ((n + G - 1) / G + 3) & ~3;   // per-CTA slice, multiple of 4

    mega_kernel<<<G, TPB>>>(logits, status, timev, out, n, lenPer);
}

// round 11
// speedup vs baseline: 1.4599x; 1.2822x over previous
#include <cuda_runtime.h>
#include <math.h>

// Cox partial likelihood (Breslow ties, mean reduction) via time-bucket histogram.
// time ∈ [0, 65536):
//   S[t] = sum_{time_i==t} exp(x_i),  m[t] = #events at t
//   D[t] = suffix sum of S,  loss = (sum_t m[t]*log(D[t]+eps) - sum_ev x)/(n_ev+eps)
//
// Round 10: HYBRID single-pass histogram. Bucket space is split across two
// concurrent atomic backends:
//   t <  SPLIT (40960, 62.5%): per-CTA smem u32 packed atomic
//       bits[0,24)=round(exp*2048), bits[24,32)=event count  (ATOMS ~2cyc/lane)
//   t >= SPLIT (37.5%):         16-way banked global u64 RED
//       bits[0,40)=round(exp*2048), bits[40,64)=event count  (L2 RED backend)
// The two backends overlap; each side carries only a fraction of the lanes.
// Single pass over input (96MB once). Integer sums -> bitwise deterministic.

#define NB      65536
#define SPLIT   40960                    // = 160 * 256, chunk-aligned
#define GBN     (NB - SPLIT)             // 24576 global-side buckets
#define NBANK   16
#define G       148
#define TPB     1024
#define NCHUNK  256
#define SPLITCH (SPLIT / 256)            // 160 chunks from smem side
#define INVSCALE (1.0 / 2048.0)

__device__ unsigned           g_part[(size_t)G * SPLIT];      // smem-side partials (23.7MB)
__device__ unsigned long long g_gtab[(size_t)NBANK * GBN];    // banked global tables (3MB)
__device__ unsigned long long g_mrg[NB];                      // merged: S | m<<40
__device__ double   g_chunkS[NCHUNK];
__device__ double   g_chunkNll[NCHUNK];
__device__ unsigned g_chunkM[NCHUNK];
__device__ float    g_evx[G];
__device__ unsigned g_barCnt[4];         // monotone barrier counters (replay-safe)

// ---------------------------------------------------------------------------
__device__ __forceinline__ void grid_barrier(int b) {
    __syncthreads();
    if (threadIdx.x == 0) {
        __threadfence();
        unsigned ticket = atomicAdd(&g_barCnt[b], 1u);
        unsigned target = (ticket / G + 1u) * G;
        while (atomicAdd(&g_barCnt[b], 0u) < target) __nanosleep(64);
    }
    __syncthreads();
}

__device__ __forceinline__ double blockReduceD(double v, double* scr) {
    int lane = threadIdx.x & 31, wid = threadIdx.x >> 5;
    #pragma unroll
    for (int o = 16; o > 0; o >>= 1) v += __shfl_down_sync(0xffffffffu, v, o);
    if (lane == 0) scr[wid] = v;
    __syncthreads();
    v = (wid == 0 && lane < TPB / 32) ? scr[lane] : 0.0;
    if (wid == 0) {
        #pragma unroll
        for (int o = 16; o > 0; o >>= 1) v += __shfl_down_sync(0xffffffffu, v, o);
    }
    return v;   // valid in thread 0
}

// ---------------------------------------------------------------------------
extern __shared__ unsigned char smem_raw[];   // SPLIT u32 = 160KB hist table

__device__ __forceinline__ void elem(int t, float xv, int sv,
                                     unsigned* sS, unsigned long long* gbank,
                                     float& ev_x) {
    // round(exp(x)*2048) = round(2^(x*log2e + 11))
    unsigned fix = __float2uint_rn(exp2f(fmaf(xv, 1.44269504f, 11.0f)));
    if (t < SPLIT) {
        atomicAdd(&sS[t], fix + ((unsigned)sv << 24));            // smem ATOMS
    } else {
        unsigned long long payload =
            (unsigned long long)fix | ((unsigned long long)(unsigned)sv << 40);
        atomicAdd(gbank + (t - SPLIT), payload);                  // global REDG.64
    }
    if (sv) ev_x += xv;
}

// ---------------------------------------------------------------------------
__global__ void __launch_bounds__(TPB, 1)
mega_kernel(const float* __restrict__ x,
            const int*   __restrict__ st,
            const int*   __restrict__ tm,
            float* __restrict__ out,
            int n, int lenPer) {
    __shared__ double             sm_buf[TPB];
    __shared__ unsigned long long sm_u64[TPB];
    __shared__ double             sm_scr[32];
    __shared__ double             sm_off;

    unsigned* sS = (unsigned*)smem_raw;
    int tid = threadIdx.x;
    int c   = blockIdx.x;

    // ---------------- Phase 0: zero smem table + global banks ----------------
    {
        uint4* s4 = (uint4*)sS;
        for (int i = tid; i < SPLIT / 4; i += TPB) s4[i] = make_uint4(0, 0, 0, 0);
        size_t total = (size_t)NBANK * GBN;
        for (size_t idx = (size_t)c * TPB + tid; idx < total; idx += (size_t)G * TPB)
            g_gtab[idx] = 0ull;
    }
    grid_barrier(0);    // also orders smem zero within CTA

    // ---------------- Phase 1: single-pass hybrid histogram ----------------
    float ev_x = 0.0f;
    {
        unsigned long long* gbank =
            g_gtab + (size_t)((((unsigned)c << 5) + (tid >> 5)) & (NBANK - 1)) * GBN;

        int s0 = min(c * lenPer, n);     // lenPer multiple of 4
        int s1 = min(s0 + lenPer, n);
        int nfull4 = (s1 - s0) >> 2;

        int g = tid;
        for (; g + TPB < nfull4; g += 2 * TPB) {
            int idx0 = s0 + g * 4;
            int idx1 = s0 + (g + TPB) * 4;
            float4 xa = __ldcs((const float4*)(x  + idx0));
            float4 xb = __ldcs((const float4*)(x  + idx1));
            int4   ta = __ldcs((const int4*)  (tm + idx0));
            int4   tb = __ldcs((const int4*)  (tm + idx1));
            int4   sa = __ldcs((const int4*)  (st + idx0));
            int4   sb = __ldcs((const int4*)  (st + idx1));
            elem(ta.x, xa.x, sa.x, sS, gbank, ev_x);
            elem(ta.y, xa.y, sa.y, sS, gbank, ev_x);
            elem(ta.z, xa.z, sa.z, sS, gbank, ev_x);
            elem(ta.w, xa.w, sa.w, sS, gbank, ev_x);
            elem(tb.x, xb.x, sb.x, sS, gbank, ev_x);
            elem(tb.y, xb.y, sb.y, sS, gbank, ev_x);
            elem(tb.z, xb.z, sb.z, sS, gbank, ev_x);
            elem(tb.w, xb.w, sb.w, sS, gbank, ev_x);
        }
        for (; g < nfull4; g += TPB) {
            int idx = s0 + g * 4;
            float4 xv = __ldcs((const float4*)(x  + idx));
            int4   tv = __ldcs((const int4*)  (tm + idx));
            int4   sv = __ldcs((const int4*)  (st + idx));
            elem(tv.x, xv.x, sv.x, sS, gbank, ev_x);
            elem(tv.y, xv.y, sv.y, sS, gbank, ev_x);
            elem(tv.z, xv.z, sv.z, sS, gbank, ev_x);
            elem(tv.w, xv.w, sv.w, sS, gbank, ev_x);
        }
        int tail0 = s0 + nfull4 * 4;
        for (int idx = tail0 + tid; idx < s1; idx += TPB)
            elem(tm[idx], x[idx], st[idx], sS, gbank, ev_x);
    }
    __syncthreads();
    // flush smem partials (plain streaming stores, no atomics)
    {
        uint4* src = (uint4*)sS;
        uint4* dst = (uint4*)(g_part + (size_t)c * SPLIT);
        for (int i = tid; i < SPLIT / 4; i += TPB) __stcs(dst + i, src[i]);
    }
    {
        double evd = blockReduceD((double)ev_x, sm_scr);
        if (tid == 0) g_evx[c] = (float)evd;
    }
    grid_barrier(1);

    // ---------------- Phase 2: merge -> g_mrg + per-chunk sums ----------------
    for (int ch = c; ch < NCHUNK; ch += G) {
        int i    = tid & 255;
        int part = tid >> 8;                    // 0..3
        unsigned long long acc = 0ull;          // S | m<<40
        if (ch < SPLITCH) {
            // smem-side bucket: sum 148 per-CTA u32-packed partials
            int t = ch * 256 + i;
            unsigned sfix = 0, m = 0;
            for (int cc = part; cc < G; cc += 4) {
                unsigned p = __ldcg(&g_part[(size_t)cc * SPLIT + t]);
                sfix += p & 0xFFFFFFu;
                m    += p >> 24;
            }
            acc = (unsigned long long)sfix | ((unsigned long long)m << 40);
        } else {
            // global-side bucket: sum 16 banks (4 per part)
            int tg = ch * 256 + i - SPLIT;
            #pragma unroll
            for (int b = 0; b < NBANK / 4; b++)
                acc += __ldcg(&g_gtab[(size_t)(part + 4 * b) * GBN + tg]);
        }
        sm_u64[tid] = acc;
        __syncthreads();
        unsigned long long tot = 0ull;
        if (part == 0) {
            tot = sm_u64[i] + sm_u64[i + 256] + sm_u64[i + 512] + sm_u64[i + 768];
            g_mrg[ch * 256 + i] = tot;
        }
        __syncthreads();
        double s = (part == 0) ? (double)(tot & 0xFFFFFFFFFFull) : 0.0;
        double m = (part == 0) ? (double)(tot >> 40) : 0.0;
        double ds = blockReduceD(s, sm_scr);
        __syncthreads();
        double dm = blockReduceD(m, sm_scr);
        if (tid == 0) {
            g_chunkS[ch] = ds * INVSCALE;
            g_chunkM[ch] = (unsigned)(dm + 0.5);
        }
        __syncthreads();
    }
    grid_barrier(2);

    // ---------------- Phase 3: per-chunk suffix scan + nll ----------------
    for (int ch = c; ch < NCHUNK; ch += G) {
        double cv = (tid < NCHUNK && tid > ch) ? __ldcg(&g_chunkS[tid]) : 0.0;
        double off = blockReduceD(cv, sm_scr);
        if (tid == 0) sm_off = off;
        __syncthreads();

        double sv = 0.0; unsigned m = 0;
        if (tid < 256) {
            unsigned long long p = __ldcg(&g_mrg[ch * 256 + tid]);
            sv = (double)(p & 0xFFFFFFFFFFull) * INVSCALE;
            m  = (unsigned)(p >> 40);
        }
        sm_buf[tid] = sv;
        __syncthreads();
        for (int o = 1; o < TPB; o <<= 1) {
            double v = (tid + o < TPB) ? sm_buf[tid + o] : 0.0;
            __syncthreads();
            sm_buf[tid] += v;
            __syncthreads();
        }
        double nll = 0.0;
        if (tid < 256 && m) {
            double D = sm_buf[tid] + sm_off;
            nll = (double)m * log(D + 1e-12);
        }
        __syncthreads();
        double tot = blockReduceD(nll, sm_scr);
        if (tid == 0) g_chunkNll[ch] = tot;
        __syncthreads();
    }
    grid_barrier(3);

    // ---------------- Phase 4: CTA 0 combines ----------------
    if (c == 0) {
        double a = (tid < NCHUNK) ? __ldcg(&g_chunkNll[tid]) : 0.0;
        double b = (tid < NCHUNK) ? (double)__ldcg(&g_chunkM[tid]) : 0.0;
        double e = (tid < G) ? (double)__ldcg(&g_evx[tid]) : 0.0;
        double nll = blockReduceD(a, sm_scr); __syncthreads();
        double nev = blockReduceD(b, sm_scr); __syncthreads();
        double evx = blockReduceD(e, sm_scr);
        if (tid == 0)
            out[0] = (float)((nll - evx) / (nev + 1e-12));
    }
}

// ---------------------------------------------------------------------------
extern "C" void kernel_launch(void* const* d_in, const int* in_sizes, int n_in,
                              void* d_out, int out_size) {
    const float* logits = (const float*)d_in[0];
    const int*   status = (const int*)d_in[1];
    const int*   timev  = (const int*)d_in[2];
    float*       out    = (float*)d_out;
    int n = in_sizes[0];

    const int SMEM_BYTES = SPLIT * sizeof(unsigned);   // 160KB
    cudaFuncSetAttribute(mega_kernel,
                         cudaFuncAttributeMaxDynamicSharedMemorySize, SMEM_BYTES);

    int lenPer = ((n + G - 1) / G + 3) & ~3;   // per-CTA slice, multiple of 4

    mega_kernel<<<G, TPB, SMEM_BYTES>>>(logits, status, timev, out, n, lenPer);
}